// round 15
// baseline (speedup 1.0000x reference)
#include <cuda_runtime.h>
#include <math.h>
#include <stdint.h>

#define PI_F 3.14159265358979323846f
#define MAX_ROWS 65536

__device__ float4 g_acc[MAX_ROWS];   // raw encoder dot products (static scratch)

__device__ __forceinline__ float2 cmul(float2 a, float2 b) {
    return make_float2(a.x*b.x - a.y*b.y, a.x*b.y + a.y*b.x);
}
__device__ __forceinline__ float2 cadd(float2 a, float2 b) {
    return make_float2(a.x + b.x, a.y + b.y);
}
// tanh via exp: abs err ~1e-7 (validated R13/R14, rel_err 7.9e-7).
__device__ __forceinline__ float tanh_fast(float x) {
    float e = __expf(2.0f * x);
    return 1.0f - 2.0f / (e + 1.0f);
}

// complex 2x2 gate on a register pair
#define GATE_PAIR(a, b, u00, u01, u10, u11) do { \
    float2 ta = (a), tb = (b); \
    (a).x = (u00).x*ta.x - (u00).y*ta.y + (u01).x*tb.x - (u01).y*tb.y; \
    (a).y = (u00).x*ta.y + (u00).y*ta.x + (u01).x*tb.y + (u01).y*tb.x; \
    (b).x = (u10).x*ta.x - (u10).y*ta.y + (u11).x*tb.x - (u11).y*tb.y; \
    (b).y = (u10).x*ta.y + (u10).y*ta.x + (u11).x*tb.y + (u11).y*tb.x; \
} while (0)

// ===================== Kernel A: encoder GEMV (unchanged, measured ~9.8us) ==
__global__ __launch_bounds__(256, 4)
void qrnn_gemv_kernel(const float* __restrict__ inputs,   // (B, 512)
                      const float* __restrict__ W_enc,    // (516, 4)
                      int B)
{
    __shared__ float4 sW[512];

    const int tid  = threadIdx.x;
    const int lane = tid & 31;
    const int wid  = tid >> 5;

    const float4* w4g = reinterpret_cast<const float4*>(W_enc);
    sW[tid]       = w4g[tid];
    sW[tid + 256] = w4g[tid + 256];
    __syncthreads();

    long r0 = (long)blockIdx.x * 16 + wid * 2;
    if (r0 + 2 > B) r0 = (B >= 2) ? (long)(B - 2) : 0;
    const float* p0 = inputs + r0 * 512 + lane;

    float xa[16], xb[16];
    #pragma unroll
    for (int m = 0; m < 16; m++) xa[m] = p0[32 * m];
    #pragma unroll
    for (int m = 0; m < 16; m++) xb[m] = p0[512 + 32 * m];

    float a0 = 0.f, a1 = 0.f, a2 = 0.f, a3 = 0.f;
    float b0 = 0.f, b1 = 0.f, b2 = 0.f, b3 = 0.f;
    #pragma unroll
    for (int m = 0; m < 16; m++) {
        float4 w = sW[lane + 32 * m];
        a0 = fmaf(xa[m], w.x, a0);
        a1 = fmaf(xa[m], w.y, a1);
        a2 = fmaf(xa[m], w.z, a2);
        a3 = fmaf(xa[m], w.w, a3);
        b0 = fmaf(xb[m], w.x, b0);
        b1 = fmaf(xb[m], w.y, b1);
        b2 = fmaf(xb[m], w.z, b2);
        b3 = fmaf(xb[m], w.w, b3);
    }

    const bool p1b = lane & 1, p2b = lane & 2;
    {
        float v01 = p1b ? a1 : a0, o01 = p1b ? a0 : a1;
        v01 += __shfl_xor_sync(0xffffffffu, o01, 1);
        float v23 = p1b ? a3 : a2, o23 = p1b ? a2 : a3;
        v23 += __shfl_xor_sync(0xffffffffu, o23, 1);
        float v = p2b ? v23 : v01, o = p2b ? v01 : v23;
        v += __shfl_xor_sync(0xffffffffu, o, 2);
        v += __shfl_xor_sync(0xffffffffu, v, 4);
        v += __shfl_xor_sync(0xffffffffu, v, 8);
        v += __shfl_xor_sync(0xffffffffu, v, 16);
        a0 = v;
    }
    {
        float v01 = p1b ? b1 : b0, o01 = p1b ? b0 : b1;
        v01 += __shfl_xor_sync(0xffffffffu, o01, 1);
        float v23 = p1b ? b3 : b2, o23 = p1b ? b2 : b3;
        v23 += __shfl_xor_sync(0xffffffffu, o23, 1);
        float v = p2b ? v23 : v01, o = p2b ? v01 : v23;
        v += __shfl_xor_sync(0xffffffffu, o, 2);
        v += __shfl_xor_sync(0xffffffffu, v, 4);
        v += __shfl_xor_sync(0xffffffffu, v, 8);
        v += __shfl_xor_sync(0xffffffffu, v, 16);
        b0 = v;
    }
    float* ga = reinterpret_cast<float*>(g_acc);
    if (lane < 4)       ga[r0 * 4 + lane] = a0;
    else if (lane < 8)  ga[(r0 + 1) * 4 + (lane & 3)] = b0;
}

// ===================== Kernel B: circuit, 2 threads per row ==================
// Thread sub = tid&1 owns the 8 amplitudes with bit3 == sub (A[j], j = b2b1b0).
// Layer-0 folded into per-qubit 2-vectors; layer-1 qubit-0 gate is the only
// cross-thread op (shfl_xor 1); CNOT q0 = predicated local swap; CNOT q1/q2 =
// compile-time renames. 64 rows/block -> 2048 warps chip-wide (2x R14).
__global__ __launch_bounds__(128)
void qrnn_circuit2_kernel(const float* __restrict__ prev_h,   // (B, 4)
                          const float* __restrict__ W_enc,    // (516, 4)
                          const float* __restrict__ b_enc,    // (4,)
                          const float* __restrict__ theta,    // (2, 4, 3)
                          const float* __restrict__ W_out,    // (4, 4)
                          const float* __restrict__ b_out,    // (4,)
                          float* __restrict__ out,            // (B, 4)
                          int B)
{
    __shared__ float2 sU[8][4];
    __shared__ float  sWtail[4][4];
    __shared__ float  sWout[16];
    __shared__ float  sbenc[4];
    __shared__ float  sbout[4];

    const int tid = threadIdx.x;

    if (tid < 8) {
        int l = tid >> 2, q = tid & 3;
        const float* th = theta + (l * 4 + q) * 3;
        float ca, sa, cb, sb, cy, sy;
        sincosf(0.5f * th[0], &sa, &ca);
        sincosf(0.5f * th[1], &sb, &cb);
        sincosf(0.5f * th[2], &sy, &cy);
        float2 RX0 = make_float2(ca, 0.f),  RX1 = make_float2(0.f, -sa);
        float2 RX2 = make_float2(0.f, -sa), RX3 = make_float2(ca, 0.f);
        float2 RZ0 = make_float2(cb, -sb),  RZ3 = make_float2(cb, sb);
        float2 M0 = cmul(RZ0, RX0);
        float2 M1 = cmul(RZ0, RX1);
        float2 M2 = cmul(RZ3, RX2);
        float2 M3 = cmul(RZ3, RX3);
        sU[tid][0] = cadd(make_float2(cy*M0.x, cy*M0.y), make_float2(-sy*M2.x, -sy*M2.y));
        sU[tid][1] = cadd(make_float2(cy*M1.x, cy*M1.y), make_float2(-sy*M3.x, -sy*M3.y));
        sU[tid][2] = cadd(make_float2(sy*M0.x, sy*M0.y), make_float2( cy*M2.x,  cy*M2.y));
        sU[tid][3] = cadd(make_float2(sy*M1.x, sy*M1.y), make_float2( cy*M3.x,  cy*M3.y));
    }
    if (tid >= 8 && tid < 12) {
        int r = tid - 8;
        sbenc[r] = b_enc[r];
        sbout[r] = b_out[r];
        #pragma unroll
        for (int j = 0; j < 4; j++)
            sWtail[r][j] = W_enc[(512 + r) * 4 + j];
    }
    if (tid >= 16 && tid < 32) sWout[tid - 16] = W_out[tid - 16];
    __syncthreads();

    const int  sub = tid & 1;
    const long row = (long)blockIdx.x * 64 + (tid >> 1);
    const long rl  = (row < B) ? row : (long)(B - 1);   // clamp loads only

    float4 pre = g_acc[rl];                                   // quad-broadcast
    float4 ph  = reinterpret_cast<const float4*>(prev_h)[rl];

    float acc[4] = {pre.x, pre.y, pre.z, pre.w};
    #pragma unroll
    for (int j = 0; j < 4; j++) {
        acc[j] += sbenc[j]
                + ph.x * sWtail[0][j] + ph.y * sWtail[1][j]
                + ph.z * sWtail[2][j] + ph.w * sWtail[3][j];
    }

    // layer-0 folding: wv[q] = U_{0,q} * RY(angle_q)|0>
    float2 wv[4][2];
    #pragma unroll
    for (int q = 0; q < 4; q++) {
        float half = tanh_fast(acc[q]) * (0.5f * PI_F);
        float c, s;
        __sincosf(half, &s, &c);
        float2 u00 = sU[q][0], u01 = sU[q][1];
        float2 u10 = sU[q][2], u11 = sU[q][3];
        wv[q][0] = make_float2(c*u00.x + s*u01.x, c*u00.y + s*u01.y);
        wv[q][1] = make_float2(c*u10.x + s*u11.x, c*u10.y + s*u11.y);
    }
    // tensor expansion of OWN amplitudes: i = sub*8 + j, j = b2 b1 b0
    float2 pre01[2], p23[4];
    pre01[0] = cmul(wv[0][sub], wv[1][0]);
    pre01[1] = cmul(wv[0][sub], wv[1][1]);
    #pragma unroll
    for (int b1 = 0; b1 < 2; b1++)
        #pragma unroll
        for (int b0 = 0; b0 < 2; b0++)
            p23[b1*2+b0] = cmul(wv[2][b1], wv[3][b0]);
    float2 A[8];
    #pragma unroll
    for (int j = 0; j < 8; j++)
        A[j] = cmul(pre01[j >> 2], p23[j & 3]);

    // ---- layer-0 CNOT chain -------------------------------------------------
    // q0: control b3=sub, target b2: sub==1 swaps j <-> j^4 (predicated)
    #pragma unroll
    for (int j = 0; j < 4; j++) {
        float2 lo = A[j], hi = A[j + 4];
        A[j]     = sub ? hi : lo;
        A[j + 4] = sub ? lo : hi;
    }
    // q1: control b2, target b1: swap (4,6) and (5,7)  [renames]
    { float2 t = A[4]; A[4] = A[6]; A[6] = t; }
    { float2 t = A[5]; A[5] = A[7]; A[7] = t; }
    // q2: control b1, target b0: swap (2,3) and (6,7)  [renames]
    { float2 t = A[2]; A[2] = A[3]; A[3] = t; }
    { float2 t = A[6]; A[6] = A[7]; A[7] = t; }

    // ---- layer-1 1q gates ---------------------------------------------------
    // q0 (mask 8): partner thread (sub^1), same j
    {
        float2 u00 = sU[4][0], u01 = sU[4][1], u10 = sU[4][2], u11 = sU[4][3];
        float2 ua = sub ? u10 : u00;
        float2 ub = sub ? u11 : u01;
        #pragma unroll
        for (int j = 0; j < 8; j++) {
            float2 o;
            o.x = __shfl_xor_sync(0xffffffffu, A[j].x, 1);
            o.y = __shfl_xor_sync(0xffffffffu, A[j].y, 1);
            float2 x = sub ? o : A[j];
            float2 y = sub ? A[j] : o;
            A[j].x = ua.x*x.x - ua.y*x.y + ub.x*y.x - ub.y*y.y;
            A[j].y = ua.x*x.y + ua.y*x.x + ub.x*y.y + ub.y*y.x;
        }
    }
    // q1 (mask 4): local pairs (j, j+4)
    {
        float2 u00 = sU[5][0], u01 = sU[5][1], u10 = sU[5][2], u11 = sU[5][3];
        #pragma unroll
        for (int j = 0; j < 4; j++) GATE_PAIR(A[j], A[j + 4], u00, u01, u10, u11);
    }
    // q2 (mask 2): local pairs (0,2),(1,3),(4,6),(5,7)
    {
        float2 u00 = sU[6][0], u01 = sU[6][1], u10 = sU[6][2], u11 = sU[6][3];
        GATE_PAIR(A[0], A[2], u00, u01, u10, u11);
        GATE_PAIR(A[1], A[3], u00, u01, u10, u11);
        GATE_PAIR(A[4], A[6], u00, u01, u10, u11);
        GATE_PAIR(A[5], A[7], u00, u01, u10, u11);
    }
    // q3 (mask 1): local pairs (0,1),(2,3),(4,5),(6,7)
    {
        float2 u00 = sU[7][0], u01 = sU[7][1], u10 = sU[7][2], u11 = sU[7][3];
        GATE_PAIR(A[0], A[1], u00, u01, u10, u11);
        GATE_PAIR(A[2], A[3], u00, u01, u10, u11);
        GATE_PAIR(A[4], A[5], u00, u01, u10, u11);
        GATE_PAIR(A[6], A[7], u00, u01, u10, u11);
    }

    // ---- layer-1 CNOT chain -------------------------------------------------
    #pragma unroll
    for (int j = 0; j < 4; j++) {
        float2 lo = A[j], hi = A[j + 4];
        A[j]     = sub ? hi : lo;
        A[j + 4] = sub ? lo : hi;
    }
    { float2 t = A[4]; A[4] = A[6]; A[6] = t; }
    { float2 t = A[5]; A[5] = A[7]; A[7] = t; }
    { float2 t = A[2]; A[2] = A[3]; A[3] = t; }
    { float2 t = A[6]; A[6] = A[7]; A[7] = t; }

    // ---- PauliZ expectations ------------------------------------------------
    float p[8];
    #pragma unroll
    for (int j = 0; j < 8; j++) p[j] = A[j].x*A[j].x + A[j].y*A[j].y;
    float s  = p[0]+p[1]+p[2]+p[3]+p[4]+p[5]+p[6]+p[7];
    float e0 = sub ? -s : s;                                   // wire0: b3=sub
    float e1 = (p[0]+p[1]+p[2]+p[3]) - (p[4]+p[5]+p[6]+p[7]);  // wire1: b2
    float e2 = (p[0]+p[1]+p[4]+p[5]) - (p[2]+p[3]+p[6]+p[7]);  // wire2: b1
    float e3 = (p[0]+p[2]+p[4]+p[6]) - (p[1]+p[3]+p[5]+p[7]);  // wire3: b0
    e0 += __shfl_xor_sync(0xffffffffu, e0, 1);
    e1 += __shfl_xor_sync(0xffffffffu, e1, 1);
    e2 += __shfl_xor_sync(0xffffffffu, e2, 1);
    e3 += __shfl_xor_sync(0xffffffffu, e3, 1);

    // ---- output: thread sub writes components 2*sub, 2*sub+1 (coalesced) ----
    const int c0 = sub * 2;
    float oc0 = tanh_fast(e0*sWout[c0]   + e1*sWout[4+c0]   + e2*sWout[8+c0]   + e3*sWout[12+c0]   + sbout[c0]);
    float oc1 = tanh_fast(e0*sWout[c0+1] + e1*sWout[5+c0]   + e2*sWout[9+c0]   + e3*sWout[13+c0]   + sbout[c0+1]);
    if (row < B)
        reinterpret_cast<float2*>(out)[row * 2 + sub] = make_float2(oc0, oc1);
}

extern "C" void kernel_launch(void* const* d_in, const int* in_sizes, int n_in,
                              void* d_out, int out_size)
{
    const float* inputs = (const float*)d_in[0];
    const float* prev_h = (const float*)d_in[1];
    const float* W_enc  = (const float*)d_in[2];
    const float* b_enc  = (const float*)d_in[3];
    const float* theta  = (const float*)d_in[4];
    const float* W_out  = (const float*)d_in[5];
    const float* b_out  = (const float*)d_in[6];

    int B = in_sizes[0] / 512;
    if (B > MAX_ROWS) B = MAX_ROWS;

    int gridA = (B + 15) / 16;
    qrnn_gemv_kernel<<<gridA, 256>>>(inputs, W_enc, B);

    int gridB = (B + 63) / 64;        // 64 rows per 128-thread block
    qrnn_circuit2_kernel<<<gridB, 128>>>(prev_h, W_enc, b_enc, theta,
                                         W_out, b_out, (float*)d_out, B);
}